// round 15
// baseline (speedup 1.0000x reference)
#include <cuda_runtime.h>
#include <cuda_fp16.h>
#include <cstdint>
#include <math.h>

// Problem dims (fixed)
#define BQ 8
#define SQ 2048
#define DQ 512
#define IQ 2048
#define MQ (BQ * SQ)            // 16384
#define BI (BQ * IQ)            // 16384

// GEMM tiling
#define BM 128
#define BN 64
#define BK 32
#define NT (DQ / BK)            // 16 k-tiles
#define NSTAGE 4

// smem stage layout (bytes): rows padded 64B->80B (stride 20 u32) for
// conflict-free fragment LDS; cp.async 16B chunks stay 16B-aligned.
#define XROW_B   80
#define X_BYTES  (BM * XROW_B)          // 10240
#define W_BYTES  (BN * XROW_B)          // 5120
#define OFF_WA   X_BYTES
#define OFF_WI   (X_BYTES + W_BYTES)
#define STAGE_B  (X_BYTES + 2 * W_BYTES)  // 20480
#define SMEM_B   (NSTAGE * STAGE_B)       // 81920

// Scratch
__device__ float  g_AC[(size_t)MQ * IQ * 2];
__device__ __half g_x16[(size_t)MQ * DQ];
__device__ __half g_wa16[(size_t)IQ * DQ];
__device__ __half g_wi16[(size_t)IQ * DQ];

__device__ __forceinline__ float sigmoidf_fast(float v) {
    return 1.0f / (1.0f + __expf(-v));
}

__device__ __forceinline__ void mma_f16(float c[4], const unsigned a[4], const unsigned b[2]) {
    asm volatile(
        "mma.sync.aligned.m16n8k16.row.col.f32.f16.f16.f32 "
        "{%0,%1,%2,%3}, {%4,%5,%6,%7}, {%8,%9}, {%0,%1,%2,%3};\n"
        : "+f"(c[0]), "+f"(c[1]), "+f"(c[2]), "+f"(c[3])
        : "r"(a[0]), "r"(a[1]), "r"(a[2]), "r"(a[3]), "r"(b[0]), "r"(b[1]));
}

__device__ __forceinline__ void cp_async16(uint32_t dst, const void* src) {
    asm volatile("cp.async.cg.shared.global [%0], [%1], 16;\n" :: "r"(dst), "l"(src));
}
#define CP_COMMIT() asm volatile("cp.async.commit_group;\n" ::: "memory")
#define CP_WAIT2()  asm volatile("cp.async.wait_group 2;\n" ::: "memory")
#define CP_WAIT0()  asm volatile("cp.async.wait_group 0;\n" ::: "memory")

// fp32 -> fp16 pre-conversion (8 elems/thread)
__global__ __launch_bounds__(256)
void cvt_kernel(const float* __restrict__ src, __half* __restrict__ dst, int n)
{
    const int i = (blockIdx.x * 256 + threadIdx.x) * 8;
    if (i >= n) return;
    float4 a = *(const float4*)(src + i);
    float4 b = *(const float4*)(src + i + 4);
    __half2 h0 = __floats2half2_rn(a.x, a.y);
    __half2 h1 = __floats2half2_rn(a.z, a.w);
    __half2 h2 = __floats2half2_rn(b.x, b.y);
    __half2 h3 = __floats2half2_rn(b.z, b.w);
    uint4 o;
    o.x = *reinterpret_cast<unsigned*>(&h0);
    o.y = *reinterpret_cast<unsigned*>(&h1);
    o.z = *reinterpret_cast<unsigned*>(&h2);
    o.w = *reinterpret_cast<unsigned*>(&h3);
    *(uint4*)(dst + i) = o;
}

// Dual-projection fp16 MMA GEMM, 4-stage cp.async pipeline + fused gate epilogue.
__global__ void __launch_bounds__(256, 2)
gemm_gate_kernel(const float* __restrict__ ba,
                 const float* __restrict__ bi,
                 const float* __restrict__ gate)
{
    extern __shared__ char smem[];
    uint32_t smem_u32;
    asm("{ .reg .u64 t; cvta.to.shared.u64 t, %1; cvt.u32.u64 %0, t; }"
        : "=r"(smem_u32) : "l"(smem));

    const int tid    = threadIdx.x;
    const int wid    = tid >> 5;
    const int lane   = tid & 31;
    const int warp_m = wid & 3;       // 4 warps over M
    const int warp_n = wid >> 2;      // 2 warps over N
    const int r      = lane >> 2;     // 0..7
    const int cq     = lane & 3;      // 0..3
    const int m0     = blockIdx.y * BM;
    const int n0     = blockIdx.x * BN;

    // load mapping: x has 512 16B-chunks/tile (2/thread), w has 256 (1/thread)
    const int xc0_row = tid >> 2,            xc0_cc = tid & 3;
    const int xc1_row = (tid + 256) >> 2,    xc1_cc = tid & 3;
    const int wc_row  = tid >> 2,            wc_cc  = tid & 3;
    const __half* xsrc0 = g_x16 + (size_t)(m0 + xc0_row) * DQ + xc0_cc * 8;
    const __half* xsrc1 = g_x16 + (size_t)(m0 + xc1_row) * DQ + xc1_cc * 8;
    const __half* wasrc = g_wa16 + (size_t)(n0 + wc_row) * DQ + wc_cc * 8;
    const __half* wisrc = g_wi16 + (size_t)(n0 + wc_row) * DQ + wc_cc * 8;
    const uint32_t xdst0 = smem_u32 + xc0_row * XROW_B + xc0_cc * 16;
    const uint32_t xdst1 = smem_u32 + xc1_row * XROW_B + xc1_cc * 16;
    const uint32_t wadst = smem_u32 + OFF_WA + wc_row * XROW_B + wc_cc * 16;
    const uint32_t widst = smem_u32 + OFF_WI + wc_row * XROW_B + wc_cc * 16;

    float acc_a[2][4][4];
    float acc_i[2][4][4];
#pragma unroll
    for (int mt = 0; mt < 2; mt++)
#pragma unroll
        for (int nt = 0; nt < 4; nt++)
#pragma unroll
            for (int e = 0; e < 4; e++) { acc_a[mt][nt][e] = 0.f; acc_i[mt][nt][e] = 0.f; }

    // ---- prologue: issue stages 0..2 ----
#pragma unroll
    for (int s = 0; s < NSTAGE - 1; s++) {
        const uint32_t so = s * STAGE_B;
        const int ko = s * BK;
        cp_async16(xdst0 + so, xsrc0 + ko);
        cp_async16(xdst1 + so, xsrc1 + ko);
        cp_async16(wadst + so, wasrc + ko);
        cp_async16(widst + so, wisrc + ko);
        CP_COMMIT();
    }

    for (int t = 0; t < NT; t++) {
        CP_WAIT2();
        __syncthreads();

        // issue tile t+3 into buffer (t+3)&3 (== buffer of finished tile t-1)
        const int tn = t + NSTAGE - 1;
        if (tn < NT) {
            const uint32_t so = (tn & 3) * STAGE_B;
            const int ko = tn * BK;
            cp_async16(xdst0 + so, xsrc0 + ko);
            cp_async16(xdst1 + so, xsrc1 + ko);
            cp_async16(wadst + so, wasrc + ko);
            cp_async16(widst + so, wisrc + ko);
        }
        CP_COMMIT();   // commit unconditionally to keep wait_group accounting

        // ---- compute stage t&3: 2 k-steps of K=16 ----
        const char* bp = smem + (t & 3) * STAGE_B;
        const unsigned* xsu = (const unsigned*)bp;
        const unsigned* wau = (const unsigned*)(bp + OFF_WA);
        const unsigned* wiu = (const unsigned*)(bp + OFF_WI);
#pragma unroll
        for (int ks = 0; ks < 2; ks++) {
            const int kb = ks * 8;
            unsigned afr[2][4];
#pragma unroll
            for (int mt = 0; mt < 2; mt++) {
                const int base = warp_m * 32 + mt * 16;
                afr[mt][0] = xsu[(base + r)     * 20 + kb + cq];
                afr[mt][1] = xsu[(base + r + 8) * 20 + kb + cq];
                afr[mt][2] = xsu[(base + r)     * 20 + kb + cq + 4];
                afr[mt][3] = xsu[(base + r + 8) * 20 + kb + cq + 4];
            }
            unsigned bfa[4][2], bfi[4][2];
#pragma unroll
            for (int nt = 0; nt < 4; nt++) {
                const int nb = warp_n * 32 + nt * 8 + r;
                bfa[nt][0] = wau[nb * 20 + kb + cq];
                bfa[nt][1] = wau[nb * 20 + kb + cq + 4];
                bfi[nt][0] = wiu[nb * 20 + kb + cq];
                bfi[nt][1] = wiu[nb * 20 + kb + cq + 4];
            }
#pragma unroll
            for (int mt = 0; mt < 2; mt++)
#pragma unroll
                for (int nt = 0; nt < 4; nt++) {
                    mma_f16(acc_a[mt][nt], afr[mt], bfa[nt]);
                    mma_f16(acc_i[mt][nt], afr[mt], bfi[nt]);
                }
        }
    }
    CP_WAIT0();

    // ---- fused gate epilogue ----
    const float LN3 = 1.0986122886681098f;
#pragma unroll
    for (int nt = 0; nt < 4; nt++) {
        const int ich0 = n0 + warp_n * 32 + nt * 8 + 2 * cq;
        const float ba0 = __ldg(ba + ich0),     ba1 = __ldg(ba + ich0 + 1);
        const float bi0 = __ldg(bi + ich0),     bi1 = __ldg(bi + ich0 + 1);
        const float al0 = sigmoidf_fast(__ldg(gate + ich0));
        const float al1 = sigmoidf_fast(__ldg(gate + ich0 + 1));
#pragma unroll
        for (int mt = 0; mt < 2; mt++) {
#pragma unroll
            for (int ro = 0; ro < 2; ro++) {
                const int m  = m0 + warp_m * 32 + mt * 16 + r + ro * 8;
                const int bb = m >> 11;
                const int ss = m & (SQ - 1);
                const int ci = ro * 2;
                float pa0 = acc_a[mt][nt][ci]     + ba0;
                float pa1 = acc_a[mt][nt][ci + 1] + ba1;
                float pi0 = acc_i[mt][nt][ci]     + bi0;
                float pi1 = acc_i[mt][nt][ci + 1] + bi1;
                float a0 = al0 * __expf(-sigmoidf_fast(pa0) * LN3);
                float a1 = al1 * __expf(-sigmoidf_fast(pa1) * LN3);
                float c0 = sqrtf(fmaxf(1.0f - a0 * a0, 0.0f)) * sigmoidf_fast(pi0) * pi0;
                float c1 = sqrtf(fmaxf(1.0f - a1 * a1, 0.0f)) * sigmoidf_fast(pi1) * pi1;
                float4 st = make_float4(a0, c0, a1, c1);
                size_t idx = (((size_t)ss * BQ + bb) * IQ + ich0) * 2;
                *(float4*)(g_AC + idx) = st;
            }
        }
    }
}

// Sequential scan: h[t] = a*h + c, double-buffered U-step batches.
#define SCAN_U 16
__global__ __launch_bounds__(128)
void scan_kernel(float* __restrict__ out)
{
    const int tid = blockIdx.x * blockDim.x + threadIdx.x;
    const int b = tid >> 11;
    const int i = tid & (IQ - 1);
    const float2* ac = ((const float2*)g_AC) + tid;
    float* o = out + (size_t)b * SQ * IQ + i;

    float2 buf[SCAN_U];
#pragma unroll
    for (int u = 0; u < SCAN_U; u++) buf[u] = ac[(size_t)u * BI];

    float h = 0.0f;
    for (int t0 = 0; t0 < SQ; t0 += SCAN_U) {
        float2 nxt[SCAN_U];
        const int tn = t0 + SCAN_U;
        if (tn < SQ) {
#pragma unroll
            for (int u = 0; u < SCAN_U; u++) nxt[u] = ac[(size_t)(tn + u) * BI];
        }
#pragma unroll
        for (int u = 0; u < SCAN_U; u++) {
            h = fmaf(buf[u].x, h, buf[u].y);
            o[(size_t)(t0 + u) * IQ] = h;
        }
#pragma unroll
        for (int u = 0; u < SCAN_U; u++) buf[u] = nxt[u];
    }
}

extern "C" void kernel_launch(void* const* d_in, const int* in_sizes, int n_in,
                              void* d_out, int out_size)
{
    const float* x    = (const float*)d_in[0];
    const float* Wa   = (const float*)d_in[1];
    const float* ba   = (const float*)d_in[2];
    const float* Wi   = (const float*)d_in[3];
    const float* bi   = (const float*)d_in[4];
    const float* gate = (const float*)d_in[5];
    float* out = (float*)d_out;

    static int smem_set = 0;
    if (!smem_set) {
        cudaFuncSetAttribute(gemm_gate_kernel,
                             cudaFuncAttributeMaxDynamicSharedMemorySize, SMEM_B);
        smem_set = 1;
    }

    __half* dx;  cudaGetSymbolAddress((void**)&dx,  g_x16);
    __half* dwa; cudaGetSymbolAddress((void**)&dwa, g_wa16);
    __half* dwi; cudaGetSymbolAddress((void**)&dwi, g_wi16);

    cvt_kernel<<<(MQ * DQ / 8 + 255) / 256, 256>>>(x,  dx,  MQ * DQ);
    cvt_kernel<<<(IQ * DQ / 8 + 255) / 256, 256>>>(Wa, dwa, IQ * DQ);
    cvt_kernel<<<(IQ * DQ / 8 + 255) / 256, 256>>>(Wi, dwi, IQ * DQ);

    dim3 grid(IQ / BN, MQ / BM);   // (32, 128)
    gemm_gate_kernel<<<grid, 256, SMEM_B>>>(ba, bi, gate);
    scan_kernel<<<BI / 128, 128>>>(out);
}

// round 16
// speedup vs baseline: 1.4341x; 1.4341x over previous
#include <cuda_runtime.h>
#include <cuda_fp16.h>
#include <cstdint>
#include <math.h>

// Problem dims (fixed)
#define BQ 8
#define SQ 2048
#define DQ 512
#define IQ 2048
#define MQ (BQ * SQ)            // 16384
#define BI (BQ * IQ)            // 16384

// GEMM tiling
#define BM 128
#define BN 64
#define BK 32
#define NT (DQ / BK)            // 16 k-tiles

// smem: rows of BK halves (64B) padded to 80B -> ldmatrix/STS conflict-free
#define XROW_B   80
#define X_BYTES  (BM * XROW_B)           // 10240
#define W_BYTES  (BN * XROW_B)           // 5120
#define OFF_WA   X_BYTES
#define OFF_WI   (X_BYTES + W_BYTES)
#define SMEM_B   (X_BYTES + 2 * W_BYTES) // 20480 (static, 2 CTAs/SM fine)

// Scratch
__device__ float  g_AC[(size_t)MQ * IQ * 2];
__device__ __half g_x16[(size_t)MQ * DQ];
__device__ __half g_wa16[(size_t)IQ * DQ];
__device__ __half g_wi16[(size_t)IQ * DQ];

__device__ __forceinline__ float sigmoidf_fast(float v) {
    return 1.0f / (1.0f + __expf(-v));
}

__device__ __forceinline__ void mma_f16(float c[4], const unsigned a[4], const unsigned b[2]) {
    asm volatile(
        "mma.sync.aligned.m16n8k16.row.col.f32.f16.f16.f32 "
        "{%0,%1,%2,%3}, {%4,%5,%6,%7}, {%8,%9}, {%0,%1,%2,%3};\n"
        : "+f"(c[0]), "+f"(c[1]), "+f"(c[2]), "+f"(c[3])
        : "r"(a[0]), "r"(a[1]), "r"(a[2]), "r"(a[3]), "r"(b[0]), "r"(b[1]));
}

__device__ __forceinline__ void ldsm4(unsigned& d0, unsigned& d1, unsigned& d2, unsigned& d3,
                                      uint32_t addr) {
    asm volatile("ldmatrix.sync.aligned.m8n8.x4.shared.b16 {%0,%1,%2,%3}, [%4];"
                 : "=r"(d0), "=r"(d1), "=r"(d2), "=r"(d3) : "r"(addr));
}

// fp32 -> fp16 pre-conversion (8 elems/thread)
__global__ __launch_bounds__(256)
void cvt_kernel(const float* __restrict__ src, __half* __restrict__ dst, int n)
{
    const int i = (blockIdx.x * 256 + threadIdx.x) * 8;
    if (i >= n) return;
    float4 a = *(const float4*)(src + i);
    float4 b = *(const float4*)(src + i + 4);
    __half2 h0 = __floats2half2_rn(a.x, a.y);
    __half2 h1 = __floats2half2_rn(a.z, a.w);
    __half2 h2 = __floats2half2_rn(b.x, b.y);
    __half2 h3 = __floats2half2_rn(b.z, b.w);
    uint4 o;
    o.x = *reinterpret_cast<unsigned*>(&h0);
    o.y = *reinterpret_cast<unsigned*>(&h1);
    o.z = *reinterpret_cast<unsigned*>(&h2);
    o.w = *reinterpret_cast<unsigned*>(&h3);
    *(uint4*)(dst + i) = o;
}

// Dual-projection fp16 MMA GEMM (round-11 reg-prefetch flow, ldmatrix fragments)
// + fused gate epilogue.
__global__ void __launch_bounds__(256, 2)
gemm_gate_kernel(const float* __restrict__ ba,
                 const float* __restrict__ bi,
                 const float* __restrict__ gate)
{
    __shared__ __align__(16) char sm[SMEM_B];
    uint32_t sm_u32;
    asm("{ .reg .u64 t; cvta.to.shared.u64 t, %1; cvt.u32.u64 %0, t; }"
        : "=r"(sm_u32) : "l"(sm));

    const int tid    = threadIdx.x;
    const int wid    = tid >> 5;
    const int lane   = tid & 31;
    const int warp_m = wid & 3;       // 4 warps over M
    const int warp_n = wid >> 2;      // 2 warps over N
    const int r      = lane >> 2;     // 0..7
    const int cq     = lane & 3;      // 0..3
    const int m0     = blockIdx.y * BM;
    const int n0     = blockIdx.x * BN;

    // ---- load mapping: 16B chunks. x: 512/tile (2/thread), w: 256 (1/thread each)
    const int xr0 = tid >> 2;             // rows 0..63
    const int xr1 = (tid + 256) >> 2;     // rows 64..127
    const int xcc = tid & 3;
    const int wr  = tid >> 2;
    const int wcc = tid & 3;
    const __half* xsrc0 = g_x16  + (size_t)(m0 + xr0) * DQ + xcc * 8;
    const __half* xsrc1 = g_x16  + (size_t)(m0 + xr1) * DQ + xcc * 8;
    const __half* wasrc = g_wa16 + (size_t)(n0 + wr)  * DQ + wcc * 8;
    const __half* wisrc = g_wi16 + (size_t)(n0 + wr)  * DQ + wcc * 8;
    char* xdst0 = sm + xr0 * XROW_B + xcc * 16;
    char* xdst1 = sm + xr1 * XROW_B + xcc * 16;
    char* wadst = sm + OFF_WA + wr * XROW_B + wcc * 16;
    char* widst = sm + OFF_WI + wr * XROW_B + wcc * 16;

    // ---- ldmatrix per-thread addresses ----
    // A x4: matrices (m0-7,k0-7),(m8-15,k0-7),(m0-7,k8-15),(m8-15,k8-15)
    const int a_row = (lane & 15);
    const uint32_t a_coff = (lane >> 4) * 16;
    uint32_t a_addr[2];
#pragma unroll
    for (int mt = 0; mt < 2; mt++)
        a_addr[mt] = sm_u32 + (warp_m * 32 + mt * 16 + a_row) * XROW_B + a_coff;
    // B x4: matrices (n0-7,k0-7),(n0-7,k8-15),(n8-15,k0-7),(n8-15,k8-15)
    const int b_row = (lane & 7) + ((lane >> 4) << 3);
    const uint32_t b_coff = ((lane >> 3) & 1) * 16;
    uint32_t ba_addr[2], bi_addr[2];
#pragma unroll
    for (int ntp = 0; ntp < 2; ntp++) {
        const int row = warp_n * 32 + ntp * 16 + b_row;
        ba_addr[ntp] = sm_u32 + OFF_WA + row * XROW_B + b_coff;
        bi_addr[ntp] = sm_u32 + OFF_WI + row * XROW_B + b_coff;
    }

    float acc_a[2][4][4];
    float acc_i[2][4][4];
#pragma unroll
    for (int mt = 0; mt < 2; mt++)
#pragma unroll
        for (int nt = 0; nt < 4; nt++)
#pragma unroll
            for (int e = 0; e < 4; e++) { acc_a[mt][nt][e] = 0.f; acc_i[mt][nt][e] = 0.f; }

    // prefetch tile 0
    uint4 px0 = *(const uint4*)xsrc0;
    uint4 px1 = *(const uint4*)xsrc1;
    uint4 pwa = *(const uint4*)wasrc;
    uint4 pwi = *(const uint4*)wisrc;

    for (int t = 0; t < NT; t++) {
        // ---- commit prefetched regs to smem ----
        *(uint4*)xdst0 = px0;
        *(uint4*)xdst1 = px1;
        *(uint4*)wadst = pwa;
        *(uint4*)widst = pwi;
        __syncthreads();

        // ---- issue next tile's global loads (hidden under MMA phase) ----
        const int ko = (t + 1) * BK;     // halves offset
        if (ko < DQ) {
            px0 = *(const uint4*)(xsrc0 + ko);
            px1 = *(const uint4*)(xsrc1 + ko);
            pwa = *(const uint4*)(wasrc + ko);
            pwi = *(const uint4*)(wisrc + ko);
        }

        // ---- MMA phase: 2 k-steps of K=16, ldmatrix fragments ----
#pragma unroll
        for (int ks = 0; ks < 2; ks++) {
            const uint32_t kso = ks * 32;   // 16 halves = 32B
            unsigned afr[2][4];
#pragma unroll
            for (int mt = 0; mt < 2; mt++)
                ldsm4(afr[mt][0], afr[mt][1], afr[mt][2], afr[mt][3], a_addr[mt] + kso);
            unsigned bfa[4][2], bfi[4][2];
#pragma unroll
            for (int ntp = 0; ntp < 2; ntp++) {
                ldsm4(bfa[ntp * 2][0], bfa[ntp * 2][1], bfa[ntp * 2 + 1][0], bfa[ntp * 2 + 1][1],
                      ba_addr[ntp] + kso);
                ldsm4(bfi[ntp * 2][0], bfi[ntp * 2][1], bfi[ntp * 2 + 1][0], bfi[ntp * 2 + 1][1],
                      bi_addr[ntp] + kso);
            }
#pragma unroll
            for (int mt = 0; mt < 2; mt++)
#pragma unroll
                for (int nt = 0; nt < 4; nt++) {
                    mma_f16(acc_a[mt][nt], afr[mt], bfa[nt]);
                    mma_f16(acc_i[mt][nt], afr[mt], bfi[nt]);
                }
        }
        __syncthreads();
    }

    // ---- fused gate epilogue ----
    const float LN3 = 1.0986122886681098f;
#pragma unroll
    for (int nt = 0; nt < 4; nt++) {
        const int ich0 = n0 + warp_n * 32 + nt * 8 + 2 * cq;
        const float ba0 = __ldg(ba + ich0),     ba1 = __ldg(ba + ich0 + 1);
        const float bi0 = __ldg(bi + ich0),     bi1 = __ldg(bi + ich0 + 1);
        const float al0 = sigmoidf_fast(__ldg(gate + ich0));
        const float al1 = sigmoidf_fast(__ldg(gate + ich0 + 1));
#pragma unroll
        for (int mt = 0; mt < 2; mt++) {
#pragma unroll
            for (int ro = 0; ro < 2; ro++) {
                const int m  = m0 + warp_m * 32 + mt * 16 + r + ro * 8;
                const int bb = m >> 11;
                const int ss = m & (SQ - 1);
                const int ci = ro * 2;
                float pa0 = acc_a[mt][nt][ci]     + ba0;
                float pa1 = acc_a[mt][nt][ci + 1] + ba1;
                float pi0 = acc_i[mt][nt][ci]     + bi0;
                float pi1 = acc_i[mt][nt][ci + 1] + bi1;
                float a0 = al0 * __expf(-sigmoidf_fast(pa0) * LN3);
                float a1 = al1 * __expf(-sigmoidf_fast(pa1) * LN3);
                float c0 = sqrtf(fmaxf(1.0f - a0 * a0, 0.0f)) * sigmoidf_fast(pi0) * pi0;
                float c1 = sqrtf(fmaxf(1.0f - a1 * a1, 0.0f)) * sigmoidf_fast(pi1) * pi1;
                float4 st = make_float4(a0, c0, a1, c1);
                size_t idx = (((size_t)ss * BQ + bb) * IQ + ich0) * 2;
                *(float4*)(g_AC + idx) = st;
            }
        }
    }
}

// Sequential scan: h[t] = a*h + c, double-buffered U-step batches.
#define SCAN_U 16
__global__ __launch_bounds__(128)
void scan_kernel(float* __restrict__ out)
{
    const int tid = blockIdx.x * blockDim.x + threadIdx.x;
    const int b = tid >> 11;
    const int i = tid & (IQ - 1);
    const float2* ac = ((const float2*)g_AC) + tid;
    float* o = out + (size_t)b * SQ * IQ + i;

    float2 buf[SCAN_U];
#pragma unroll
    for (int u = 0; u < SCAN_U; u++) buf[u] = ac[(size_t)u * BI];

    float h = 0.0f;
    for (int t0 = 0; t0 < SQ; t0 += SCAN_U) {
        float2 nxt[SCAN_U];
        const int tn = t0 + SCAN_U;
        if (tn < SQ) {
#pragma unroll
            for (int u = 0; u < SCAN_U; u++) nxt[u] = ac[(size_t)(tn + u) * BI];
        }
#pragma unroll
        for (int u = 0; u < SCAN_U; u++) {
            h = fmaf(buf[u].x, h, buf[u].y);
            o[(size_t)(t0 + u) * IQ] = h;
        }
#pragma unroll
        for (int u = 0; u < SCAN_U; u++) buf[u] = nxt[u];
    }
}

extern "C" void kernel_launch(void* const* d_in, const int* in_sizes, int n_in,
                              void* d_out, int out_size)
{
    const float* x    = (const float*)d_in[0];
    const float* Wa   = (const float*)d_in[1];
    const float* ba   = (const float*)d_in[2];
    const float* Wi   = (const float*)d_in[3];
    const float* bi   = (const float*)d_in[4];
    const float* gate = (const float*)d_in[5];
    float* out = (float*)d_out;

    __half* dx;  cudaGetSymbolAddress((void**)&dx,  g_x16);
    __half* dwa; cudaGetSymbolAddress((void**)&dwa, g_wa16);
    __half* dwi; cudaGetSymbolAddress((void**)&dwi, g_wi16);

    cvt_kernel<<<(MQ * DQ / 8 + 255) / 256, 256>>>(x,  dx,  MQ * DQ);
    cvt_kernel<<<(IQ * DQ / 8 + 255) / 256, 256>>>(Wa, dwa, IQ * DQ);
    cvt_kernel<<<(IQ * DQ / 8 + 255) / 256, 256>>>(Wi, dwi, IQ * DQ);

    dim3 grid(IQ / BN, MQ / BM);   // (32, 128)
    gemm_gate_kernel<<<grid, 256>>>(ba, bi, gate);
    scan_kernel<<<BI / 128, 128>>>(out);
}